// round 1
// baseline (speedup 1.0000x reference)
#include <cuda_runtime.h>
#include <cstdint>

// Problem constants (fixed by dataset shapes)
#define D        64
#define NMAX     200000
#define DOUT     256      // 4 layers * 64

// Scratch (device globals: allocation-free, harness-legal)
__device__ float g_ego [(size_t)NMAX * D];          // 51.2 MB  (unnormalized layer input)
__device__ float g_side[(size_t)NMAX * D];          // 51.2 MB  (segment_sum result)
__device__ float g_all [(size_t)NMAX * DOUT];       // 204.8 MB (concatenated embeddings)

// ---------------------------------------------------------------------------
// Init: ego0 = concat(user_emb, item_emb); all[:, 0:64] = ego0 (unnormalized)
// ---------------------------------------------------------------------------
__global__ void init_kernel(const float* __restrict__ ue,
                            const float* __restrict__ ie,
                            int n_users, int N) {
    int tid = blockIdx.x * blockDim.x + threadIdx.x;   // over N*16 float4
    if (tid >= N * 16) return;
    int n = tid >> 4;
    int c = tid & 15;
    float4 v = (n < n_users)
        ? reinterpret_cast<const float4*>(ue)[(size_t)n * 16 + c]
        : reinterpret_cast<const float4*>(ie)[(size_t)(n - n_users) * 16 + c];
    reinterpret_cast<float4*>(g_ego)[(size_t)n * 16 + c] = v;
    // all row = 256 floats = 64 float4; layer-0 slice = first 16 float4
    reinterpret_cast<float4*>(g_all)[(size_t)n * 64 + c] = v;
}

// ---------------------------------------------------------------------------
// Zero side buffer
// ---------------------------------------------------------------------------
__global__ void zero_side_kernel(int N) {
    int tid = blockIdx.x * blockDim.x + threadIdx.x;   // over N*16 float4
    if (tid >= N * 16) return;
    reinterpret_cast<float4*>(g_side)[tid] = make_float4(0.f, 0.f, 0.f, 0.f);
}

// ---------------------------------------------------------------------------
// SpMM scatter: side[rows[e]] += vals[e] * ego[cols[e]]
// One thread per (edge, 16B chunk): 16 consecutive threads share one edge,
// so the 256B ego-row gather and the 128-bit atomics are fully coalesced.
// ---------------------------------------------------------------------------
__global__ void scatter_kernel(const int* __restrict__ rows,
                               const int* __restrict__ cols,
                               const float* __restrict__ vals,
                               int nnz) {
    int tid = blockIdx.x * blockDim.x + threadIdx.x;   // over nnz*16
    if (tid >= nnz * 16) return;
    int e = tid >> 4;
    int c = tid & 15;
    int r  = rows[e];
    int co = cols[e];
    float v = vals[e];
    float4 x = reinterpret_cast<const float4*>(g_ego)[(size_t)co * 16 + c];
    float4 y = make_float4(v * x.x, v * x.y, v * x.z, v * x.w);
    atomicAdd(reinterpret_cast<float4*>(g_side) + (size_t)r * 16 + c, y);
}

// ---------------------------------------------------------------------------
// Fused transform per layer:
//   sum = side @ W_gc + b_gc ; bi = (ego*side) @ W_bi + b_bi
//   act = leaky_relu(sum+bi, 0.2)
//   ego <- act (unnormalized, next-layer input)
//   all[:, 64*layer_out : +64] <- act / max(||act||_2, 1e-12)
// One warp per node; lane l owns output cols {2l, 2l+1}; W in shared.
// ---------------------------------------------------------------------------
__global__ void transform_kernel(const float* __restrict__ Wg,
                                 const float* __restrict__ bg,
                                 const float* __restrict__ Wb,
                                 const float* __restrict__ bb,
                                 int N, int layer_out) {
    __shared__ float sWg[64 * 64];
    __shared__ float sWb[64 * 64];
    for (int i = threadIdx.x; i < 64 * 64; i += blockDim.x) {
        sWg[i] = Wg[i];
        sWb[i] = Wb[i];
    }
    __syncthreads();

    const int lane   = threadIdx.x & 31;
    const int warp   = (blockIdx.x * blockDim.x + threadIdx.x) >> 5;
    const int nwarps = (gridDim.x * blockDim.x) >> 5;

    const float bias0 = bg[2 * lane]     + bb[2 * lane];
    const float bias1 = bg[2 * lane + 1] + bb[2 * lane + 1];

    for (int n = warp; n < N; n += nwarps) {
        const float* sr = g_side + (size_t)n * D;
        const float* er = g_ego  + (size_t)n * D;
        float s0  = sr[lane];
        float s1  = sr[lane + 32];
        float es0 = er[lane]      * s0;
        float es1 = er[lane + 32] * s1;

        float a0 = bias0, a1 = bias1;
        #pragma unroll
        for (int c = 0; c < 32; c++) {
            float s  = __shfl_sync(0xffffffffu, s0,  c);
            float es = __shfl_sync(0xffffffffu, es0, c);
            float2 wg = reinterpret_cast<const float2*>(sWg + c * 64)[lane];
            float2 wb = reinterpret_cast<const float2*>(sWb + c * 64)[lane];
            a0 += s * wg.x + es * wb.x;
            a1 += s * wg.y + es * wb.y;
        }
        #pragma unroll
        for (int c = 0; c < 32; c++) {
            float s  = __shfl_sync(0xffffffffu, s1,  c);
            float es = __shfl_sync(0xffffffffu, es1, c);
            float2 wg = reinterpret_cast<const float2*>(sWg + (c + 32) * 64)[lane];
            float2 wb = reinterpret_cast<const float2*>(sWb + (c + 32) * 64)[lane];
            a0 += s * wg.x + es * wb.x;
            a1 += s * wg.y + es * wb.y;
        }

        // leaky_relu 0.2
        a0 = (a0 > 0.f) ? a0 : 0.2f * a0;
        a1 = (a1 > 0.f) ? a1 : 0.2f * a1;

        // row L2 norm over 64 cols
        float sq = a0 * a0 + a1 * a1;
        #pragma unroll
        for (int off = 16; off; off >>= 1)
            sq += __shfl_xor_sync(0xffffffffu, sq, off);
        float inv = 1.0f / fmaxf(sqrtf(sq), 1e-12f);

        reinterpret_cast<float2*>(g_ego + (size_t)n * D)[lane] =
            make_float2(a0, a1);
        reinterpret_cast<float2*>(g_all + (size_t)n * DOUT + layer_out * D)[lane] =
            make_float2(a0 * inv, a1 * inv);
    }
}

// ---------------------------------------------------------------------------
// Final gather: out = [ all[u] ; all[n_users+i] ; all[n_users+j] ], each B x 256
// ---------------------------------------------------------------------------
__global__ void gather_kernel(const int* __restrict__ u,
                              const int* __restrict__ ii,
                              const int* __restrict__ jj,
                              float* __restrict__ out,
                              int B, int n_users) {
    int tid = blockIdx.x * blockDim.x + threadIdx.x;   // over 3*B*64 float4
    if (tid >= 3 * B * 64) return;
    int c     = tid & 63;
    int b     = (tid >> 6) % B;
    int which = tid / (B * 64);
    int node  = (which == 0) ? u[b]
              : (which == 1) ? n_users + ii[b]
                             : n_users + jj[b];
    reinterpret_cast<float4*>(out)[tid] =
        reinterpret_cast<const float4*>(g_all)[(size_t)node * 64 + c];
}

// ---------------------------------------------------------------------------
extern "C" void kernel_launch(void* const* d_in, const int* in_sizes, int n_in,
                              void* d_out, int out_size) {
    const int*   rows = (const int*)  d_in[0];
    const int*   cols = (const int*)  d_in[1];
    const float* vals = (const float*)d_in[2];
    const float* ue   = (const float*)d_in[3];
    const float* ie   = (const float*)d_in[4];
    const float* Wgc  = (const float*)d_in[5];
    const float* bgc  = (const float*)d_in[6];
    const float* Wbi  = (const float*)d_in[7];
    const float* bbi  = (const float*)d_in[8];
    const int*   u    = (const int*)  d_in[9];
    const int*   ii   = (const int*)  d_in[10];
    const int*   jj   = (const int*)  d_in[11];

    const int nnz     = in_sizes[0];
    const int n_users = in_sizes[3] / D;
    const int n_items = in_sizes[4] / D;
    const int N       = n_users + n_items;
    const int B       = in_sizes[9];
    const int layers  = in_sizes[5] / (D * D);   // 3

    const int TPB = 256;

    init_kernel<<<(N * 16 + TPB - 1) / TPB, TPB>>>(ue, ie, n_users, N);

    for (int k = 0; k < layers; k++) {
        zero_side_kernel<<<(N * 16 + TPB - 1) / TPB, TPB>>>(N);
        {
            long long total = (long long)nnz * 16;
            int blocks = (int)((total + TPB - 1) / TPB);
            scatter_kernel<<<blocks, TPB>>>(rows, cols, vals, nnz);
        }
        transform_kernel<<<2048, TPB>>>(Wgc + (size_t)k * D * D,
                                        bgc + (size_t)k * D,
                                        Wbi + (size_t)k * D * D,
                                        bbi + (size_t)k * D,
                                        N, k + 1);
    }

    gather_kernel<<<(3 * B * 64 + TPB - 1) / TPB, TPB>>>(u, ii, jj,
                                                         (float*)d_out, B, n_users);
}

// round 3
// speedup vs baseline: 1.9203x; 1.9203x over previous
#include <cuda_runtime.h>
#include <cstdint>

#define D        64
#define NMAX     200000
#define NNZMAX   6400000
#define DOUT     256
#define NBLK_MAX 1024   // scan blocks: ceil(200000/256)=782

// Scratch (device globals: allocation-free)
__device__ float g_ego [(size_t)NMAX * D];
__device__ float g_side[(size_t)NMAX * D];
__device__ float g_all [(size_t)NMAX * DOUT];
__device__ int   g_cnt [NMAX];
__device__ int   g_scan[NMAX];
__device__ int   g_rowptr[NMAX + 1];
__device__ int   g_bsum[NBLK_MAX];
__device__ int   g_bsumscan[NBLK_MAX];
__device__ int   g_ecol[NNZMAX];
__device__ float g_eval[NNZMAX];

// ---------------------------------------------------------------------------
// CSR build
// ---------------------------------------------------------------------------
__global__ void zero_cnt_kernel(int N) {
    int i = blockIdx.x * blockDim.x + threadIdx.x;
    if (i < N) g_cnt[i] = 0;
}

__global__ void hist_kernel(const int* __restrict__ rows, int nnz) {
    int e = blockIdx.x * blockDim.x + threadIdx.x;
    if (e < nnz) atomicAdd(&g_cnt[rows[e]], 1);
}

// per-block exclusive scan of g_cnt (block = 256 elems), block sums to g_bsum
__global__ void scan_block_kernel(int N) {
    __shared__ int sh[256];
    int i = blockIdx.x * 256 + threadIdx.x;
    int v = (i < N) ? g_cnt[i] : 0;
    sh[threadIdx.x] = v;
    __syncthreads();
    for (int off = 1; off < 256; off <<= 1) {
        int t = (threadIdx.x >= off) ? sh[threadIdx.x - off] : 0;
        __syncthreads();
        sh[threadIdx.x] += t;
        __syncthreads();
    }
    if (i < N) g_scan[i] = sh[threadIdx.x] - v;
    if (threadIdx.x == 255) g_bsum[blockIdx.x] = sh[255];
}

// single-block exclusive scan of g_bsum (nb <= 1024)
__global__ void scan_top_kernel(int nb) {
    __shared__ int sh[NBLK_MAX];
    int i = threadIdx.x;
    int v = (i < nb) ? g_bsum[i] : 0;
    sh[i] = v;
    __syncthreads();
    for (int off = 1; off < NBLK_MAX; off <<= 1) {
        int t = (i >= off) ? sh[i - off] : 0;
        __syncthreads();
        sh[i] += t;
        __syncthreads();
    }
    if (i < nb) g_bsumscan[i] = sh[i] - v;
}

// rowptr = scan + block offset; rowptr[N] = nnz; re-zero g_cnt for fill pass
__global__ void rowptr_kernel(int N, int nnz) {
    int i = blockIdx.x * blockDim.x + threadIdx.x;
    if (i < N) {
        g_rowptr[i] = g_scan[i] + g_bsumscan[i >> 8];
        g_cnt[i] = 0;
    } else if (i == N) {
        g_rowptr[N] = nnz;
    }
}

__global__ void fill_kernel(const int* __restrict__ rows,
                            const int* __restrict__ cols,
                            const float* __restrict__ vals, int nnz) {
    int e = blockIdx.x * blockDim.x + threadIdx.x;
    if (e >= nnz) return;
    int r = rows[e];
    int p = atomicAdd(&g_cnt[r], 1);
    int d = g_rowptr[r] + p;
    g_ecol[d] = cols[e];
    g_eval[d] = vals[e];
}

// ---------------------------------------------------------------------------
// Init: ego0 = concat(user_emb, item_emb); all[:, 0:64] = ego0
// ---------------------------------------------------------------------------
__global__ void init_kernel(const float* __restrict__ ue,
                            const float* __restrict__ ie,
                            int n_users, int N) {
    int tid = blockIdx.x * blockDim.x + threadIdx.x;
    if (tid >= N * 16) return;
    int n = tid >> 4;
    int c = tid & 15;
    float4 v = (n < n_users)
        ? reinterpret_cast<const float4*>(ue)[(size_t)n * 16 + c]
        : reinterpret_cast<const float4*>(ie)[(size_t)(n - n_users) * 16 + c];
    reinterpret_cast<float4*>(g_ego)[(size_t)n * 16 + c] = v;
    reinterpret_cast<float4*>(g_all)[(size_t)n * 64 + c] = v;
}

// ---------------------------------------------------------------------------
// Pull-mode SpMM: side[r] = sum_{e in row r} val[e] * ego[col[e]]
// 16 threads per row (thread c owns float4 chunk c); no atomics, no zero pass.
// ---------------------------------------------------------------------------
__global__ void spmm_csr_kernel(int N) {
    int gid = blockIdx.x * blockDim.x + threadIdx.x;
    int row = gid >> 4;
    int c   = gid & 15;
    if (row >= N) return;
    int e   = g_rowptr[row];
    int end = g_rowptr[row + 1];
    const float4* ego4 = reinterpret_cast<const float4*>(g_ego);
    float4 acc = make_float4(0.f, 0.f, 0.f, 0.f);
    for (; e + 1 < end; e += 2) {
        int   c0 = g_ecol[e],  c1 = g_ecol[e + 1];
        float v0 = g_eval[e],  v1 = g_eval[e + 1];
        float4 x0 = ego4[(size_t)c0 * 16 + c];
        float4 x1 = ego4[(size_t)c1 * 16 + c];
        acc.x += v0 * x0.x + v1 * x1.x;
        acc.y += v0 * x0.y + v1 * x1.y;
        acc.z += v0 * x0.z + v1 * x1.z;
        acc.w += v0 * x0.w + v1 * x1.w;
    }
    if (e < end) {
        int   c0 = g_ecol[e];
        float v0 = g_eval[e];
        float4 x0 = ego4[(size_t)c0 * 16 + c];
        acc.x += v0 * x0.x; acc.y += v0 * x0.y;
        acc.z += v0 * x0.z; acc.w += v0 * x0.w;
    }
    reinterpret_cast<float4*>(g_side)[(size_t)row * 16 + c] = acc;
}

// ---------------------------------------------------------------------------
// Fused transform, 4 nodes per warp per iteration (amortizes weight LDS 4x)
// ---------------------------------------------------------------------------
__global__ void transform_kernel(const float* __restrict__ Wg,
                                 const float* __restrict__ bg,
                                 const float* __restrict__ Wb,
                                 const float* __restrict__ bb,
                                 int N, int layer_out) {
    __shared__ float sWg[64 * 64];
    __shared__ float sWb[64 * 64];
    for (int i = threadIdx.x; i < 64 * 64; i += blockDim.x) {
        sWg[i] = Wg[i];
        sWb[i] = Wb[i];
    }
    __syncthreads();

    const int lane   = threadIdx.x & 31;
    const int warp   = (blockIdx.x * blockDim.x + threadIdx.x) >> 5;
    const int nwarps = (gridDim.x * blockDim.x) >> 5;

    const float bias0 = bg[2 * lane]     + bb[2 * lane];
    const float bias1 = bg[2 * lane + 1] + bb[2 * lane + 1];

    for (int n0 = warp * 4; n0 < N; n0 += nwarps * 4) {
        float s0[4], s1[4], es0[4], es1[4], a0[4], a1[4];
        #pragma unroll
        for (int t = 0; t < 4; t++) {
            int n = n0 + t; if (n >= N) n = N - 1;   // clamp; duplicate compute, guarded write
            const float* sr = g_side + (size_t)n * D;
            const float* er = g_ego  + (size_t)n * D;
            s0[t]  = sr[lane];
            s1[t]  = sr[lane + 32];
            es0[t] = er[lane]      * s0[t];
            es1[t] = er[lane + 32] * s1[t];
            a0[t] = bias0; a1[t] = bias1;
        }

        #pragma unroll
        for (int c = 0; c < 32; c++) {
            float2 wg = reinterpret_cast<const float2*>(sWg + c * 64)[lane];
            float2 wb = reinterpret_cast<const float2*>(sWb + c * 64)[lane];
            #pragma unroll
            for (int t = 0; t < 4; t++) {
                float s  = __shfl_sync(0xffffffffu, s0[t],  c);
                float es = __shfl_sync(0xffffffffu, es0[t], c);
                a0[t] += s * wg.x + es * wb.x;
                a1[t] += s * wg.y + es * wb.y;
            }
        }
        #pragma unroll
        for (int c = 0; c < 32; c++) {
            float2 wg = reinterpret_cast<const float2*>(sWg + (c + 32) * 64)[lane];
            float2 wb = reinterpret_cast<const float2*>(sWb + (c + 32) * 64)[lane];
            #pragma unroll
            for (int t = 0; t < 4; t++) {
                float s  = __shfl_sync(0xffffffffu, s1[t],  c);
                float es = __shfl_sync(0xffffffffu, es1[t], c);
                a0[t] += s * wg.x + es * wb.x;
                a1[t] += s * wg.y + es * wb.y;
            }
        }

        #pragma unroll
        for (int t = 0; t < 4; t++) {
            int n = n0 + t;
            float x0 = a0[t], x1 = a1[t];
            x0 = (x0 > 0.f) ? x0 : 0.2f * x0;
            x1 = (x1 > 0.f) ? x1 : 0.2f * x1;
            float sq = x0 * x0 + x1 * x1;
            #pragma unroll
            for (int off = 16; off; off >>= 1)
                sq += __shfl_xor_sync(0xffffffffu, sq, off);
            float inv = 1.0f / fmaxf(sqrtf(sq), 1e-12f);
            if (n < N) {
                reinterpret_cast<float2*>(g_ego + (size_t)n * D)[lane] =
                    make_float2(x0, x1);
                reinterpret_cast<float2*>(g_all + (size_t)n * DOUT + layer_out * D)[lane] =
                    make_float2(x0 * inv, x1 * inv);
            }
        }
    }
}

// ---------------------------------------------------------------------------
// Final gather
// ---------------------------------------------------------------------------
__global__ void gather_kernel(const int* __restrict__ u,
                              const int* __restrict__ ii,
                              const int* __restrict__ jj,
                              float* __restrict__ out,
                              int B, int n_users) {
    int tid = blockIdx.x * blockDim.x + threadIdx.x;
    if (tid >= 3 * B * 64) return;
    int c     = tid & 63;
    int b     = (tid >> 6) % B;
    int which = tid / (B * 64);
    int node  = (which == 0) ? u[b]
              : (which == 1) ? n_users + ii[b]
                             : n_users + jj[b];
    reinterpret_cast<float4*>(out)[tid] =
        reinterpret_cast<const float4*>(g_all)[(size_t)node * 64 + c];
}

// ---------------------------------------------------------------------------
extern "C" void kernel_launch(void* const* d_in, const int* in_sizes, int n_in,
                              void* d_out, int out_size) {
    const int*   rows = (const int*)  d_in[0];
    const int*   cols = (const int*)  d_in[1];
    const float* vals = (const float*)d_in[2];
    const float* ue   = (const float*)d_in[3];
    const float* ie   = (const float*)d_in[4];
    const float* Wgc  = (const float*)d_in[5];
    const float* bgc  = (const float*)d_in[6];
    const float* Wbi  = (const float*)d_in[7];
    const float* bbi  = (const float*)d_in[8];
    const int*   u    = (const int*)  d_in[9];
    const int*   ii   = (const int*)  d_in[10];
    const int*   jj   = (const int*)  d_in[11];

    const int nnz     = in_sizes[0];
    const int n_users = in_sizes[3] / D;
    const int n_items = in_sizes[4] / D;
    const int N       = n_users + n_items;
    const int B       = in_sizes[9];
    const int layers  = in_sizes[5] / (D * D);

    const int TPB = 256;
    const int nb  = (N + 255) / 256;

    // CSR build (once per launch, reused by all 3 layers)
    zero_cnt_kernel<<<(N + TPB - 1) / TPB, TPB>>>(N);
    hist_kernel<<<(nnz + TPB - 1) / TPB, TPB>>>(rows, nnz);
    scan_block_kernel<<<nb, 256>>>(N);
    scan_top_kernel<<<1, NBLK_MAX>>>(nb);
    rowptr_kernel<<<(N + 1 + TPB - 1) / TPB, TPB>>>(N, nnz);
    fill_kernel<<<(nnz + TPB - 1) / TPB, TPB>>>(rows, cols, vals, nnz);

    init_kernel<<<(N * 16 + TPB - 1) / TPB, TPB>>>(ue, ie, n_users, N);

    for (int k = 0; k < layers; k++) {
        spmm_csr_kernel<<<(N * 16 + TPB - 1) / TPB, TPB>>>(N);
        transform_kernel<<<2048, TPB>>>(Wgc + (size_t)k * D * D,
                                        bgc + (size_t)k * D,
                                        Wbi + (size_t)k * D * D,
                                        bbi + (size_t)k * D,
                                        N, k + 1);
    }

    gather_kernel<<<(3 * B * 64 + TPB - 1) / TPB, TPB>>>(u, ii, jj,
                                                         (float*)d_out, B, n_users);
}

// round 5
// speedup vs baseline: 2.2922x; 1.1937x over previous
#include <cuda_runtime.h>
#include <cuda_fp16.h>
#include <cstdint>

#define D        64
#define NMAX     200000
#define NNZMAX   6400000
#define DOUT     256
#define NBLK_MAX 1024

// Scratch (device globals: allocation-free)
__device__ float  g_ego [(size_t)NMAX * D];        // fp32 ego (transform input)
__device__ __half g_egoh[(size_t)NMAX * D];        // fp16 ego (SpMM gather operand)
__device__ float  g_side[(size_t)NMAX * D];
__device__ float  g_all [(size_t)NMAX * DOUT];
__device__ int    g_cnt [NMAX];
__device__ int    g_scan[NMAX];
__device__ int    g_rowptr[NMAX + 1];
__device__ int    g_bsum[NBLK_MAX];
__device__ int    g_bsumscan[NBLK_MAX];
__device__ int    g_ecol[NNZMAX];
__device__ float  g_eval[NNZMAX];

// ---------------------------------------------------------------------------
// CSR build
// ---------------------------------------------------------------------------
__global__ void zero_cnt_kernel(int N) {
    int i = blockIdx.x * blockDim.x + threadIdx.x;
    if (i < N) g_cnt[i] = 0;
}

__global__ void hist_kernel(const int* __restrict__ rows, int nnz) {
    int e = blockIdx.x * blockDim.x + threadIdx.x;
    if (e < nnz) atomicAdd(&g_cnt[rows[e]], 1);
}

__global__ void scan_block_kernel(int N) {
    __shared__ int sh[256];
    int i = blockIdx.x * 256 + threadIdx.x;
    int v = (i < N) ? g_cnt[i] : 0;
    sh[threadIdx.x] = v;
    __syncthreads();
    for (int off = 1; off < 256; off <<= 1) {
        int t = (threadIdx.x >= off) ? sh[threadIdx.x - off] : 0;
        __syncthreads();
        sh[threadIdx.x] += t;
        __syncthreads();
    }
    if (i < N) g_scan[i] = sh[threadIdx.x] - v;
    if (threadIdx.x == 255) g_bsum[blockIdx.x] = sh[255];
}

__global__ void scan_top_kernel(int nb) {
    __shared__ int sh[NBLK_MAX];
    int i = threadIdx.x;
    int v = (i < nb) ? g_bsum[i] : 0;
    sh[i] = v;
    __syncthreads();
    for (int off = 1; off < NBLK_MAX; off <<= 1) {
        int t = (i >= off) ? sh[i - off] : 0;
        __syncthreads();
        sh[i] += t;
        __syncthreads();
    }
    if (i < nb) g_bsumscan[i] = sh[i] - v;
}

__global__ void rowptr_kernel(int N, int nnz) {
    int i = blockIdx.x * blockDim.x + threadIdx.x;
    if (i < N) {
        g_rowptr[i] = g_scan[i] + g_bsumscan[i >> 8];
        g_cnt[i] = 0;
    } else if (i == N) {
        g_rowptr[N] = nnz;
    }
}

__global__ void fill_kernel(const int* __restrict__ rows,
                            const int* __restrict__ cols,
                            const float* __restrict__ vals, int nnz) {
    int e = blockIdx.x * blockDim.x + threadIdx.x;
    if (e >= nnz) return;
    int r = rows[e];
    int p = atomicAdd(&g_cnt[r], 1);
    int d = g_rowptr[r] + p;
    g_ecol[d] = cols[e];
    g_eval[d] = vals[e];
}

// ---------------------------------------------------------------------------
// Init: ego0 = concat(user_emb, item_emb); fp16 copy; all[:, 0:64] = ego0
// ---------------------------------------------------------------------------
__global__ void init_kernel(const float* __restrict__ ue,
                            const float* __restrict__ ie,
                            int n_users, int N) {
    int tid = blockIdx.x * blockDim.x + threadIdx.x;
    if (tid >= N * 16) return;
    int n = tid >> 4;
    int c = tid & 15;
    float4 v = (n < n_users)
        ? reinterpret_cast<const float4*>(ue)[(size_t)n * 16 + c]
        : reinterpret_cast<const float4*>(ie)[(size_t)(n - n_users) * 16 + c];
    reinterpret_cast<float4*>(g_ego)[(size_t)n * 16 + c] = v;
    reinterpret_cast<float4*>(g_all)[(size_t)n * 64 + c] = v;
    __half2* hr = reinterpret_cast<__half2*>(g_egoh) + (size_t)n * 32 + c * 2;
    hr[0] = __floats2half2_rn(v.x, v.y);
    hr[1] = __floats2half2_rn(v.z, v.w);
}

// ---------------------------------------------------------------------------
// Pull-mode SpMM with fp16 gather operand:
//   side[r] = sum_e val[e] * fp32(egoh[col[e]])
// 8 threads per row; thread c owns 8 halfs (16B chunk c).
// ---------------------------------------------------------------------------
__device__ __forceinline__ void fma8h(float* acc, uint4 x, float v) {
    float2 f;
    f = __half22float2(*reinterpret_cast<__half2*>(&x.x)); acc[0] += v * f.x; acc[1] += v * f.y;
    f = __half22float2(*reinterpret_cast<__half2*>(&x.y)); acc[2] += v * f.x; acc[3] += v * f.y;
    f = __half22float2(*reinterpret_cast<__half2*>(&x.z)); acc[4] += v * f.x; acc[5] += v * f.y;
    f = __half22float2(*reinterpret_cast<__half2*>(&x.w)); acc[6] += v * f.x; acc[7] += v * f.y;
}

__global__ void spmm_csr_kernel(int N) {
    int gid = blockIdx.x * blockDim.x + threadIdx.x;
    int row = gid >> 3;
    int c   = gid & 7;
    if (row >= N) return;
    int e   = g_rowptr[row];
    int end = g_rowptr[row + 1];
    const uint4* egoh = reinterpret_cast<const uint4*>(g_egoh);  // 16B = 8 halfs
    float acc[8] = {0.f, 0.f, 0.f, 0.f, 0.f, 0.f, 0.f, 0.f};
    for (; e + 1 < end; e += 2) {
        int   c0 = g_ecol[e],  c1 = g_ecol[e + 1];
        float v0 = g_eval[e],  v1 = g_eval[e + 1];
        uint4 x0 = egoh[(size_t)c0 * 8 + c];
        uint4 x1 = egoh[(size_t)c1 * 8 + c];
        fma8h(acc, x0, v0);
        fma8h(acc, x1, v1);
    }
    if (e < end) {
        uint4 x0 = egoh[(size_t)g_ecol[e] * 8 + c];
        fma8h(acc, x0, g_eval[e]);
    }
    float4* out = reinterpret_cast<float4*>(g_side) + (size_t)row * 16 + c * 2;
    out[0] = make_float4(acc[0], acc[1], acc[2], acc[3]);
    out[1] = make_float4(acc[4], acc[5], acc[6], acc[7]);
}

// ---------------------------------------------------------------------------
// Fused transform, 4 nodes/warp; writes fp32 ego, fp16 ego copy, normalized all
// ---------------------------------------------------------------------------
__global__ void transform_kernel(const float* __restrict__ Wg,
                                 const float* __restrict__ bg,
                                 const float* __restrict__ Wb,
                                 const float* __restrict__ bb,
                                 int N, int layer_out) {
    __shared__ float sWg[64 * 64];
    __shared__ float sWb[64 * 64];
    for (int i = threadIdx.x; i < 64 * 64; i += blockDim.x) {
        sWg[i] = Wg[i];
        sWb[i] = Wb[i];
    }
    __syncthreads();

    const int lane   = threadIdx.x & 31;
    const int warp   = (blockIdx.x * blockDim.x + threadIdx.x) >> 5;
    const int nwarps = (gridDim.x * blockDim.x) >> 5;

    const float bias0 = bg[2 * lane]     + bb[2 * lane];
    const float bias1 = bg[2 * lane + 1] + bb[2 * lane + 1];

    for (int n0 = warp * 4; n0 < N; n0 += nwarps * 4) {
        float s0[4], s1[4], es0[4], es1[4], a0[4], a1[4];
        #pragma unroll
        for (int t = 0; t < 4; t++) {
            int n = n0 + t; if (n >= N) n = N - 1;
            const float* sr = g_side + (size_t)n * D;
            const float* er = g_ego  + (size_t)n * D;
            s0[t]  = sr[lane];
            s1[t]  = sr[lane + 32];
            es0[t] = er[lane]      * s0[t];
            es1[t] = er[lane + 32] * s1[t];
            a0[t] = bias0; a1[t] = bias1;
        }

        #pragma unroll
        for (int c = 0; c < 32; c++) {
            float2 wg = reinterpret_cast<const float2*>(sWg + c * 64)[lane];
            float2 wb = reinterpret_cast<const float2*>(sWb + c * 64)[lane];
            #pragma unroll
            for (int t = 0; t < 4; t++) {
                float s  = __shfl_sync(0xffffffffu, s0[t],  c);
                float es = __shfl_sync(0xffffffffu, es0[t], c);
                a0[t] += s * wg.x + es * wb.x;
                a1[t] += s * wg.y + es * wb.y;
            }
        }
        #pragma unroll
        for (int c = 0; c < 32; c++) {
            float2 wg = reinterpret_cast<const float2*>(sWg + (c + 32) * 64)[lane];
            float2 wb = reinterpret_cast<const float2*>(sWb + (c + 32) * 64)[lane];
            #pragma unroll
            for (int t = 0; t < 4; t++) {
                float s  = __shfl_sync(0xffffffffu, s1[t],  c);
                float es = __shfl_sync(0xffffffffu, es1[t], c);
                a0[t] += s * wg.x + es * wb.x;
                a1[t] += s * wg.y + es * wb.y;
            }
        }

        #pragma unroll
        for (int t = 0; t < 4; t++) {
            int n = n0 + t;
            float x0 = a0[t], x1 = a1[t];
            x0 = (x0 > 0.f) ? x0 : 0.2f * x0;
            x1 = (x1 > 0.f) ? x1 : 0.2f * x1;
            float sq = x0 * x0 + x1 * x1;
            #pragma unroll
            for (int off = 16; off; off >>= 1)
                sq += __shfl_xor_sync(0xffffffffu, sq, off);
            float inv = 1.0f / fmaxf(sqrtf(sq), 1e-12f);
            if (n < N) {
                reinterpret_cast<float2*>(g_ego + (size_t)n * D)[lane] =
                    make_float2(x0, x1);
                reinterpret_cast<__half2*>(g_egoh + (size_t)n * D)[lane] =
                    __floats2half2_rn(x0, x1);
                reinterpret_cast<float2*>(g_all + (size_t)n * DOUT + layer_out * D)[lane] =
                    make_float2(x0 * inv, x1 * inv);
            }
        }
    }
}

// ---------------------------------------------------------------------------
// Final gather
// ---------------------------------------------------------------------------
__global__ void gather_kernel(const int* __restrict__ u,
                              const int* __restrict__ ii,
                              const int* __restrict__ jj,
                              float* __restrict__ out,
                              int B, int n_users) {
    int tid = blockIdx.x * blockDim.x + threadIdx.x;
    if (tid >= 3 * B * 64) return;
    int c     = tid & 63;
    int b     = (tid >> 6) % B;
    int which = tid / (B * 64);
    int node  = (which == 0) ? u[b]
              : (which == 1) ? n_users + ii[b]
                             : n_users + jj[b];
    reinterpret_cast<float4*>(out)[tid] =
        reinterpret_cast<const float4*>(g_all)[(size_t)node * 64 + c];
}

// ---------------------------------------------------------------------------
extern "C" void kernel_launch(void* const* d_in, const int* in_sizes, int n_in,
                              void* d_out, int out_size) {
    const int*   rows = (const int*)  d_in[0];
    const int*   cols = (const int*)  d_in[1];
    const float* vals = (const float*)d_in[2];
    const float* ue   = (const float*)d_in[3];
    const float* ie   = (const float*)d_in[4];
    const float* Wgc  = (const float*)d_in[5];
    const float* bgc  = (const float*)d_in[6];
    const float* Wbi  = (const float*)d_in[7];
    const float* bbi  = (const float*)d_in[8];
    const int*   u    = (const int*)  d_in[9];
    const int*   ii   = (const int*)  d_in[10];
    const int*   jj   = (const int*)  d_in[11];

    const int nnz     = in_sizes[0];
    const int n_users = in_sizes[3] / D;
    const int n_items = in_sizes[4] / D;
    const int N       = n_users + n_items;
    const int B       = in_sizes[9];
    const int layers  = in_sizes[5] / (D * D);

    const int TPB = 256;
    const int nb  = (N + 255) / 256;

    zero_cnt_kernel<<<(N + TPB - 1) / TPB, TPB>>>(N);
    hist_kernel<<<(nnz + TPB - 1) / TPB, TPB>>>(rows, nnz);
    scan_block_kernel<<<nb, 256>>>(N);
    scan_top_kernel<<<1, NBLK_MAX>>>(nb);
    rowptr_kernel<<<(N + 1 + TPB - 1) / TPB, TPB>>>(N, nnz);
    fill_kernel<<<(nnz + TPB - 1) / TPB, TPB>>>(rows, cols, vals, nnz);

    init_kernel<<<(N * 16 + TPB - 1) / TPB, TPB>>>(ue, ie, n_users, N);

    for (int k = 0; k < layers; k++) {
        spmm_csr_kernel<<<(N * 8 + TPB - 1) / TPB, TPB>>>(N);
        transform_kernel<<<2048, TPB>>>(Wgc + (size_t)k * D * D,
                                        bgc + (size_t)k * D,
                                        Wbi + (size_t)k * D * D,
                                        bbi + (size_t)k * D,
                                        N, k + 1);
    }

    gather_kernel<<<(3 * B * 64 + TPB - 1) / TPB, TPB>>>(u, ii, jj,
                                                         (float*)d_out, B, n_users);
}